// round 7
// baseline (speedup 1.0000x reference)
#include <cuda_runtime.h>
#include <cuda_bf16.h>

// Shapes: B=32, S=2048, I=128, A=128, H=256, K=8, ACTIVE=3 (structurally k=0,1,2)
#define NB 32
#define NS 2048
#define NI 128
#define NA 128
#define NH 256
#define NK 8
#define KACT 3
#define CHUNKS 16
#define ROWS_PER_BLOCK (NS / CHUNKS)       // 128
#define PREF 4

#define NBLK_Q    (KACT * 4)               // 12: q partials
#define NBLK_U    (KACT)                   // 3 : u
#define NBLK_H    (KACT * 4)               // 12: hpre
#define NBLK_PRE  (NBLK_Q + NBLK_U + NBLK_H)      // 27
#define NBLK_MAIN (NB * CHUNKS)            // 512
#define NBLK      (NBLK_PRE + NBLK_MAIN)   // 539

typedef unsigned long long ull;

// Device scratch (allocation-free rule: __device__ globals; zero-initialized)
__device__ float g_qpart[KACT][4][NA];
__device__ float g_u[KACT][NI];
__device__ float g_hpre[KACT][NH];
__device__ __align__(16) float g_ypart[NB][CHUNKS][KACT * NI];
__device__ int   g_qcnt[KACT];
__device__ int   g_ucnt;

__device__ __forceinline__ void spin_until(int* p, int target) {
    while (*(volatile int*)p < target) __nanosleep(32);
}

// ---- packed f32x2 helpers (sm_100+; PTX-only, ptxas never auto-fuses) ----
__device__ __forceinline__ void fma2(ull& d, ull a, ull b) {
    asm("fma.rn.f32x2 %0, %1, %2, %0;" : "+l"(d) : "l"(a), "l"(b));
}
__device__ __forceinline__ ull add2(ull a, ull b) {
    ull d; asm("add.rn.f32x2 %0, %1, %2;" : "=l"(d) : "l"(a), "l"(b)); return d;
}
__device__ __forceinline__ float2 unpack2(ull v) {
    float2 r; asm("mov.b64 {%0, %1}, %2;" : "=f"(r.x), "=f"(r.y) : "l"(v)); return r;
}
__device__ __forceinline__ ull pack2(float lo, float hi) {
    ull r; asm("mov.b64 %0, {%1, %2};" : "=l"(r) : "f"(lo), "f"(hi)); return r;
}

// ===========================================================================
// Kernel A: prologue (27 blocks) + main (512 blocks), intra-grid flag sync.
// ===========================================================================
__global__ __launch_bounds__(256) void fused_main_kernel(
    const float* __restrict__ x,   const float* __restrict__ rim,
    const float* __restrict__ Wq,  const float* __restrict__ Wk,
    const float* __restrict__ Whh, const float* __restrict__ bias)
{
    const int tid = threadIdx.x;
    const int bid = blockIdx.x;

    if (bid >= NBLK_PRE) {
        // ================= MAIN (two-phase, packed f32x2) =================
        __shared__ __align__(16) float us[KACT][160];        // u halves at 0 / 80 (bank-split)
        __shared__ ull dd[KACT][ROWS_PER_BLOCK];             // d duplicated as (d,d)
        __shared__ __align__(16) ull ysw[8][KACT * (NI / 2)];// per-warp packed y partials

        const int mb    = bid - NBLK_PRE;
        const int b     = mb >> 4;
        const int chunk = mb & 15;
        const size_t rowbase = (size_t)b * NS + chunk * ROWS_PER_BLOCK;

        // --- phase 1 setup: 2 threads per row, 64 elems each
        const int row  = tid >> 1;
        const int half = tid & 1;
        const ulonglong2* __restrict__ xp1 =
            reinterpret_cast<const ulonglong2*>(x + (rowbase + row) * NI + half * 64);

        // prefetch keeps memory busy while prologue finishes
        ulonglong2 pf[PREF];
        #pragma unroll
        for (int j = 0; j < PREF; ++j) pf[j] = xp1[j];

        if (tid == 0) spin_until(&g_ucnt, KACT);
        __syncthreads();

        // stage u into smem (padded halves: bank-disjoint for even/odd lanes)
        for (int t = tid; t < KACT * NI; t += 256) {
            const int k = t >> 7, i = t & 127;
            us[k][(i >> 6) * 80 + (i & 63)] = __ldcg(&g_u[k][i]);
        }
        __syncthreads();

        // --- phase 1: d[k][row] = x[row] . u[k]
        {
            const ulonglong2* __restrict__ u0p =
                reinterpret_cast<const ulonglong2*>(&us[0][half * 80]);
            const ulonglong2* __restrict__ u1p =
                reinterpret_cast<const ulonglong2*>(&us[1][half * 80]);
            const ulonglong2* __restrict__ u2p =
                reinterpret_cast<const ulonglong2*>(&us[2][half * 80]);

            ull a00 = 0, a01 = 0, a10 = 0, a11 = 0, a20 = 0, a21 = 0;
            #pragma unroll
            for (int j = 0; j < 16; ++j) {
                const ulonglong2 xv = (j < PREF) ? pf[j] : xp1[j];
                const ulonglong2 u0v = u0p[j], u1v = u1p[j], u2v = u2p[j];
                fma2(a00, xv.x, u0v.x); fma2(a01, xv.y, u0v.y);
                fma2(a10, xv.x, u1v.x); fma2(a11, xv.y, u1v.y);
                fma2(a20, xv.x, u2v.x); fma2(a21, xv.y, u2v.y);
            }
            const float2 f0 = unpack2(add2(a00, a01));
            const float2 f1 = unpack2(add2(a10, a11));
            const float2 f2 = unpack2(add2(a20, a21));
            float s0 = f0.x + f0.y, s1 = f1.x + f1.y, s2 = f2.x + f2.y;
            s0 += __shfl_xor_sync(0xffffffffu, s0, 1);
            s1 += __shfl_xor_sync(0xffffffffu, s1, 1);
            s2 += __shfl_xor_sync(0xffffffffu, s2, 1);
            if (half == 0) {
                dd[0][row] = pack2(s0, s0);
                dd[1][row] = pack2(s1, s1);
                dd[2][row] = pack2(s2, s2);
            }
        }
        __syncthreads();

        // --- phase 2: y[k][c] += d[k][r] * x[r][c]   (x re-read: L1 hits)
        const int warp = tid >> 5, lane = tid & 31;
        {
            const ulonglong2* __restrict__ xp2 =
                reinterpret_cast<const ulonglong2*>(x + (rowbase + warp * 16) * NI) + lane;
            ull y00 = 0, y01 = 0, y10 = 0, y11 = 0, y20 = 0, y21 = 0;
            #pragma unroll
            for (int r = 0; r < 16; ++r) {
                const ulonglong2 xv = xp2[r * 32];
                const ull d0 = dd[0][warp * 16 + r];
                const ull d1 = dd[1][warp * 16 + r];
                const ull d2 = dd[2][warp * 16 + r];
                fma2(y00, xv.x, d0); fma2(y01, xv.y, d0);
                fma2(y10, xv.x, d1); fma2(y11, xv.y, d1);
                fma2(y20, xv.x, d2); fma2(y21, xv.y, d2);
            }
            reinterpret_cast<ulonglong2*>(&ysw[warp][0 * 64])[lane] = make_ulonglong2(y00, y01);
            reinterpret_cast<ulonglong2*>(&ysw[warp][1 * 64])[lane] = make_ulonglong2(y10, y11);
            reinterpret_cast<ulonglong2*>(&ysw[warp][2 * 64])[lane] = make_ulonglong2(y20, y21);
        }
        __syncthreads();

        // --- cross-warp combine (packed), 96 x ulonglong2 outputs
        if (tid < 96) {
            const ulonglong2* __restrict__ base =
                reinterpret_cast<const ulonglong2*>(ysw);   // [8][96] units
            ulonglong2 v = base[tid];
            ull slo = v.x, shi = v.y;
            #pragma unroll
            for (int w = 1; w < 8; ++w) {
                const ulonglong2 t2 = base[w * 96 + tid];
                slo = add2(slo, t2.x);
                shi = add2(shi, t2.y);
            }
            reinterpret_cast<ulonglong2*>(&g_ypart[b][chunk][0])[tid] =
                make_ulonglong2(slo, shi);
        }
    } else if (bid < NBLK_Q) {
        // ---- q partials: block (k, p), h in [p*64, p*64+64)
        __shared__ __align__(16) float qp[2][NA];
        const int k = bid >> 2, p = bid & 3;
        const int a = tid & 127, sub = tid >> 7;
        const int h0 = p * 64 + sub * 32;
        const float* __restrict__ wq = Wq + ((size_t)(k * NH + h0)) * NA + a;
        const float* __restrict__ rk = rim + k * NH + h0;
        float acc0 = 0.f, acc1 = 0.f, acc2 = 0.f, acc3 = 0.f;
        #pragma unroll
        for (int h = 0; h < 32; h += 4) {
            acc0 += rk[h + 0] * wq[(size_t)(h + 0) * NA];
            acc1 += rk[h + 1] * wq[(size_t)(h + 1) * NA];
            acc2 += rk[h + 2] * wq[(size_t)(h + 2) * NA];
            acc3 += rk[h + 3] * wq[(size_t)(h + 3) * NA];
        }
        qp[sub][a] = (acc0 + acc1) + (acc2 + acc3);
        __syncthreads();
        if (tid < NA) g_qpart[k][p][tid] = qp[0][tid] + qp[1][tid];
        __threadfence();
        __syncthreads();
        if (tid == 0) atomicAdd(&g_qcnt[k], 1);
    } else if (bid < NBLK_Q + NBLK_U) {
        // ---- u[k][i] = Wk[k][i][:].q
        __shared__ __align__(16) float qs[NA];
        const int k = bid - NBLK_Q;
        const int warp = tid >> 5, lane = tid & 31;
        const float4* __restrict__ wkbase =
            reinterpret_cast<const float4*>(Wk + ((size_t)k * NI) * NA);
        float4 w4[16];
        #pragma unroll
        for (int ii = 0; ii < 16; ++ii)
            w4[ii] = wkbase[(size_t)(warp * 16 + ii) * 32 + lane];

        if (tid == 0) spin_until(&g_qcnt[k], 4);
        __syncthreads();

        if (tid < NA) {
            qs[tid] = (__ldcg(&g_qpart[k][0][tid]) + __ldcg(&g_qpart[k][1][tid]))
                    + (__ldcg(&g_qpart[k][2][tid]) + __ldcg(&g_qpart[k][3][tid]));
        }
        __syncthreads();
        const float4 q4 = reinterpret_cast<const float4*>(qs)[lane];
        #pragma unroll
        for (int ii = 0; ii < 16; ++ii) {
            float p = w4[ii].x * q4.x + w4[ii].y * q4.y + w4[ii].z * q4.z + w4[ii].w * q4.w;
            #pragma unroll
            for (int off = 16; off; off >>= 1) p += __shfl_xor_sync(0xffffffffu, p, off);
            if (lane == 0) g_u[k][warp * 16 + ii] = p;
        }
        __threadfence();
        __syncthreads();
        if (tid == 0) atomicAdd(&g_ucnt, 1);
    } else {
        // ---- hpre: consumed only by epilogue kernel — no flag needed
        __shared__ float hs[4][64];
        const int idx = bid - NBLK_Q - NBLK_U;
        const int k = idx >> 2, hq = idx & 3;
        const int h = hq * 64 + (tid & 63);
        const int part = tid >> 6;
        const float* __restrict__ rk = rim + k * NH + part * 64;
        const float* __restrict__ wh = Whh + (size_t)(part * 64) * NH + h;
        float acc0 = 0.f, acc1 = 0.f, acc2 = 0.f, acc3 = 0.f;
        #pragma unroll
        for (int hp = 0; hp < 64; hp += 4) {
            acc0 += rk[hp + 0] * wh[(size_t)(hp + 0) * NH];
            acc1 += rk[hp + 1] * wh[(size_t)(hp + 1) * NH];
            acc2 += rk[hp + 2] * wh[(size_t)(hp + 2) * NH];
            acc3 += rk[hp + 3] * wh[(size_t)(hp + 3) * NH];
        }
        hs[part][tid & 63] = (acc0 + acc1) + (acc2 + acc3);
        __syncthreads();
        if (tid < 64) {
            g_hpre[k][h] = bias[h] +
                ((hs[0][tid] + hs[1][tid]) + (hs[2][tid] + hs[3][tid]));
        }
    }
}

// ===========================================================================
// Kernel B: epilogue (32 blocks x 1024). Runs after A (stream order).
// Block 0 also resets A's sync counters for the next graph replay.
// ===========================================================================
__global__ __launch_bounds__(1024) void epilogue_kernel(
    const float* __restrict__ rim, const float* __restrict__ Wv,
    const float* __restrict__ Wih, float* __restrict__ out)
{
    const int b = blockIdx.x;
    const int tid = threadIdx.x;

    if (b == 0 && tid < 4) {
        if (tid < KACT) g_qcnt[tid] = 0;
        else            g_ucnt = 0;
    }

    __shared__ float ys[KACT * NI];
    __shared__ float attp[2][KACT * NA];
    __shared__ float att[KACT * NA];

    // ---- y: 384 outputs, 16 fully-unrolled loads each
    if (tid < KACT * NI) {
        const float* yp = &g_ypart[b][0][0];
        float s0 = yp[0 * (KACT * NI) + tid];
        float s1 = yp[1 * (KACT * NI) + tid];
        float s2 = yp[2 * (KACT * NI) + tid];
        float s3 = yp[3 * (KACT * NI) + tid];
        #pragma unroll
        for (int c = 4; c < CHUNKS; c += 4) {
            s0 += yp[(c + 0) * (KACT * NI) + tid];
            s1 += yp[(c + 1) * (KACT * NI) + tid];
            s2 += yp[(c + 2) * (KACT * NI) + tid];
            s3 += yp[(c + 3) * (KACT * NI) + tid];
        }
        ys[tid] = (s0 + s1) + (s2 + s3);
    }
    __syncthreads();

    // ---- att[k][a] = sum_i Wv[k][i][a]*ys[k][i]; 2-way split over i
    if (tid < 2 * KACT * NA) {
        const int half = tid / (KACT * NA);
        const int jj   = tid - half * (KACT * NA);
        const int k = jj >> 7, a = jj & 127;
        const float* __restrict__ wv =
            Wv + (size_t)k * NI * NA + (size_t)(half * 64) * NA + a;
        const float* __restrict__ yk = ys + k * NI + half * 64;
        float c0 = 0.f, c1 = 0.f, c2 = 0.f, c3 = 0.f;
        #pragma unroll
        for (int i = 0; i < 64; i += 4) {
            c0 += wv[(size_t)(i + 0) * NA] * yk[i + 0];
            c1 += wv[(size_t)(i + 1) * NA] * yk[i + 1];
            c2 += wv[(size_t)(i + 2) * NA] * yk[i + 2];
            c3 += wv[(size_t)(i + 3) * NA] * yk[i + 3];
        }
        attp[half][jj] = (c0 + c1) + (c2 + c3);
    }
    __syncthreads();
    if (tid < KACT * NA) att[tid] = attp[0][tid] + attp[1][tid];
    __syncthreads();

    float* ob = out + (size_t)b * NK * NH;

    // ---- cand: 768 outputs, one thread each
    if (tid < KACT * NH) {
        const int k = tid >> 8, h = tid & 255;
        const float* __restrict__ ak = att + k * NA;
        const float* __restrict__ wih = Wih + h;
        float c0 = g_hpre[k][h], c1 = 0.f, c2 = 0.f, c3 = 0.f;
        #pragma unroll
        for (int a = 0; a < NA; a += 4) {
            c0 += ak[a + 0] * wih[(size_t)(a + 0) * NH];
            c1 += ak[a + 1] * wih[(size_t)(a + 1) * NH];
            c2 += ak[a + 2] * wih[(size_t)(a + 2) * NH];
            c3 += ak[a + 3] * wih[(size_t)(a + 3) * NH];
        }
        ob[tid] = tanhf((c0 + c1) + (c2 + c3));
    }
    // ---- k = 3..7: passthrough rim_hidden
    for (int j = tid; j < (NK - KACT) * NH; j += 1024) {
        ob[KACT * NH + j] = rim[KACT * NH + j];
    }
}

// ---------------------------------------------------------------------------
extern "C" void kernel_launch(void* const* d_in, const int* in_sizes, int n_in,
                              void* d_out, int out_size)
{
    const float* x    = (const float*)d_in[0];
    const float* rim  = (const float*)d_in[1];
    const float* Wq   = (const float*)d_in[2];
    const float* Wk   = (const float*)d_in[3];
    const float* Wv   = (const float*)d_in[4];
    const float* Wih  = (const float*)d_in[5];
    const float* Whh  = (const float*)d_in[6];
    const float* bias = (const float*)d_in[7];
    float* out = (float*)d_out;

    fused_main_kernel<<<NBLK, 256>>>(x, rim, Wq, Wk, Whh, bias);
    epilogue_kernel<<<NB, 1024>>>(rim, Wv, Wih, out);
}

// round 8
// speedup vs baseline: 1.6842x; 1.6842x over previous
#include <cuda_runtime.h>
#include <cuda_bf16.h>

// Shapes: B=32, S=2048, I=128, A=128, H=256, K=8, ACTIVE=3 (structurally k=0,1,2)
#define NB 32
#define NS 2048
#define NI 128
#define NA 128
#define NH 256
#define NK 8
#define KACT 3
#define CHUNKS 32
#define ROWS_PER_BLOCK (NS / CHUNKS)       // 64
#define ROWS_PER_WARP (ROWS_PER_BLOCK / 8) // 8

// Device scratch (allocation-free rule: __device__ globals)
__device__ float g_u[KACT][NI];
__device__ float g_hpre[KACT][NH];
__device__ __align__(16) float g_ypart[NB][CHUNKS][KACT * NI];

// ---------------------------------------------------------------------------
// Prologue (R4 design: 9 blocks x 1024 threads, no inter-block sync):
//   blocks 0..2 : k-block. q[k][a] = sum_h rim*Wq (128a x 8 parts x 32 loads)
//                 then u[k][i] = Wk[k][i][:].q    (4 rows per warp)
//   blocks 3..8 : (k, h-half) hpre (128h x 8 parts x 32 loads)
// ---------------------------------------------------------------------------
__global__ __launch_bounds__(1024) void prologue_kernel(
    const float* __restrict__ rim, const float* __restrict__ Wq,
    const float* __restrict__ Wk, const float* __restrict__ Whh,
    const float* __restrict__ bias)
{
    const int tid = threadIdx.x;
    const int bid = blockIdx.x;

    if (bid < KACT) {
        const int k = bid;
        __shared__ float qp[8][NA];
        __shared__ __align__(16) float qs[NA];

        // ---- stage 1: q partials, 32 fully-unrolled independent loads/thread
        {
            const int a    = tid & 127;
            const int part = tid >> 7;           // 0..7
            const int h0   = part * 32;
            const float* __restrict__ wq = Wq + ((size_t)(k * NH + h0)) * NA + a;
            const float* __restrict__ rk = rim + k * NH + h0;
            float acc0 = 0.f, acc1 = 0.f, acc2 = 0.f, acc3 = 0.f;
            #pragma unroll
            for (int h = 0; h < 32; h += 4) {
                acc0 += rk[h + 0] * wq[(size_t)(h + 0) * NA];
                acc1 += rk[h + 1] * wq[(size_t)(h + 1) * NA];
                acc2 += rk[h + 2] * wq[(size_t)(h + 2) * NA];
                acc3 += rk[h + 3] * wq[(size_t)(h + 3) * NA];
            }
            qp[part][a] = (acc0 + acc1) + (acc2 + acc3);
        }
        __syncthreads();
        if (tid < NA) {
            qs[tid] = ((qp[0][tid] + qp[1][tid]) + (qp[2][tid] + qp[3][tid]))
                    + ((qp[4][tid] + qp[5][tid]) + (qp[6][tid] + qp[7][tid]));
        }
        __syncthreads();

        // ---- stage 2: u[k][i]; 32 warps x 4 rows, one float4/lane per row
        const int warp = tid >> 5, lane = tid & 31;
        const float4 q4 = reinterpret_cast<const float4*>(qs)[lane];
        const float4* __restrict__ wkbase =
            reinterpret_cast<const float4*>(Wk + ((size_t)k * NI) * NA);
        #pragma unroll
        for (int ii = 0; ii < 4; ++ii) {
            const int i = warp * 4 + ii;
            const float4 w4 = wkbase[(size_t)i * 32 + lane];
            float p = w4.x * q4.x + w4.y * q4.y + w4.z * q4.z + w4.w * q4.w;
            #pragma unroll
            for (int off = 16; off; off >>= 1) p += __shfl_xor_sync(0xffffffffu, p, off);
            if (lane == 0) g_u[k][i] = p;
        }
    } else {
        // ---- hpre: block (k, half). 128h x 8 parts x 32 loads = 1 batch
        const int idx  = bid - KACT;
        const int k    = idx >> 1;
        const int half = idx & 1;
        const int h    = half * 128 + (tid & 127);
        const int part = tid >> 7;               // 0..7
        const float* __restrict__ rk = rim + k * NH + part * 32;
        const float* __restrict__ wh = Whh + (size_t)(part * 32) * NH + h;

        float acc0 = 0.f, acc1 = 0.f, acc2 = 0.f, acc3 = 0.f;
        #pragma unroll
        for (int hp = 0; hp < 32; hp += 4) {
            acc0 += rk[hp + 0] * wh[(size_t)(hp + 0) * NH];
            acc1 += rk[hp + 1] * wh[(size_t)(hp + 1) * NH];
            acc2 += rk[hp + 2] * wh[(size_t)(hp + 2) * NH];
            acc3 += rk[hp + 3] * wh[(size_t)(hp + 3) * NH];
        }
        __shared__ float hp_s[8][128];
        hp_s[part][tid & 127] = (acc0 + acc1) + (acc2 + acc3);
        __syncthreads();
        if (tid < 128) {
            float s = ((hp_s[0][tid] + hp_s[1][tid]) + (hp_s[2][tid] + hp_s[3][tid]))
                    + ((hp_s[4][tid] + hp_s[5][tid]) + (hp_s[6][tid] + hp_s[7][tid]));
            g_hpre[k][half * 128 + tid] = bias[half * 128 + tid] + s;
        }
    }
}

// ---------------------------------------------------------------------------
// Main: y[b][k][i] = sum_s x[b][s][i] * (x[b][s] . u[k]),  k = 0..2
// 1024 blocks x 256 thr (~7 blocks/SM -> ~86% occupancy), 8 rows per warp.
// ---------------------------------------------------------------------------
__global__ __launch_bounds__(256) void main_kernel(const float* __restrict__ x)
{
    const int b     = blockIdx.x >> 5;
    const int chunk = blockIdx.x & 31;
    const int warp  = threadIdx.x >> 5;
    const int lane  = threadIdx.x & 31;

    const size_t row0 = (size_t)b * NS + chunk * ROWS_PER_BLOCK + warp * ROWS_PER_WARP;
    const float4* __restrict__ xr = reinterpret_cast<const float4*>(x + row0 * NI) + lane;

    const float4 u0 = reinterpret_cast<const float4*>(g_u[0])[lane];
    const float4 u1 = reinterpret_cast<const float4*>(g_u[1])[lane];
    const float4 u2 = reinterpret_cast<const float4*>(g_u[2])[lane];

    float4 a0 = make_float4(0.f, 0.f, 0.f, 0.f);
    float4 a1 = a0, a2 = a0;

    #pragma unroll
    for (int r = 0; r < ROWS_PER_WARP; ++r) {
        const float4 v = xr[r * 32];
        float d0 = v.x * u0.x + v.y * u0.y + v.z * u0.z + v.w * u0.w;
        float d1 = v.x * u1.x + v.y * u1.y + v.z * u1.z + v.w * u1.w;
        float d2 = v.x * u2.x + v.y * u2.y + v.z * u2.z + v.w * u2.w;
        #pragma unroll
        for (int off = 16; off; off >>= 1) {
            d0 += __shfl_xor_sync(0xffffffffu, d0, off);
            d1 += __shfl_xor_sync(0xffffffffu, d1, off);
            d2 += __shfl_xor_sync(0xffffffffu, d2, off);
        }
        a0.x += d0 * v.x; a0.y += d0 * v.y; a0.z += d0 * v.z; a0.w += d0 * v.w;
        a1.x += d1 * v.x; a1.y += d1 * v.y; a1.z += d1 * v.z; a1.w += d1 * v.w;
        a2.x += d2 * v.x; a2.y += d2 * v.y; a2.z += d2 * v.z; a2.w += d2 * v.w;
    }

    __shared__ __align__(16) float ysw[8][KACT * NI];
    reinterpret_cast<float4*>(&ysw[warp][0 * NI])[lane] = a0;
    reinterpret_cast<float4*>(&ysw[warp][1 * NI])[lane] = a1;
    reinterpret_cast<float4*>(&ysw[warp][2 * NI])[lane] = a2;
    __syncthreads();

    // cross-warp combine: 96 float4 outputs
    if (threadIdx.x < 96) {
        const float4* __restrict__ base = reinterpret_cast<const float4*>(ysw);
        float4 s = base[threadIdx.x];
        #pragma unroll
        for (int w = 1; w < 8; ++w) {
            const float4 t = base[w * 96 + threadIdx.x];
            s.x += t.x; s.y += t.y; s.z += t.z; s.w += t.w;
        }
        reinterpret_cast<float4*>(&g_ypart[b][chunk][0])[threadIdx.x] = s;
    }
}

// ---------------------------------------------------------------------------
// Epilogue: 96 blocks (b, k) x 512 thr; all reduces 4-way split, <=16-deep.
// ---------------------------------------------------------------------------
__global__ __launch_bounds__(512) void epilogue_kernel(
    const float* __restrict__ rim, const float* __restrict__ Wv,
    const float* __restrict__ Wih, float* __restrict__ out)
{
    const int bid = blockIdx.x;
    const int b = bid / KACT;
    const int k = bid - b * KACT;
    const int tid = threadIdx.x;

    __shared__ float ysp[4][NI];
    __shared__ float ys[NI];
    __shared__ float attp[4][NA];
    __shared__ float att[NA];
    __shared__ float candp[2][NH];

    // ---- ys[i] = sum over 32 chunks of g_ypart[b][c][k*128+i]; 4-way chunk split
    {
        const int part = tid >> 7;            // 0..3 -> chunks [part*8, part*8+8)
        const int i    = tid & 127;
        const float* __restrict__ yp = &g_ypart[b][part * 8][k * NI + i];
        float s0 = yp[0 * (KACT * NI)] + yp[1 * (KACT * NI)];
        float s1 = yp[2 * (KACT * NI)] + yp[3 * (KACT * NI)];
        float s2 = yp[4 * (KACT * NI)] + yp[5 * (KACT * NI)];
        float s3 = yp[6 * (KACT * NI)] + yp[7 * (KACT * NI)];
        ysp[part][i] = (s0 + s1) + (s2 + s3);
    }
    __syncthreads();
    if (tid < NI)
        ys[tid] = (ysp[0][tid] + ysp[1][tid]) + (ysp[2][tid] + ysp[3][tid]);
    __syncthreads();

    // ---- att[a] = sum_i Wv[k][i][a] * ys[i]; 4-way i split (32 loads each)
    {
        const int part = tid >> 7;            // i in [part*32, part*32+32)
        const int a    = tid & 127;
        const float* __restrict__ wv = Wv + (size_t)k * NI * NA + (size_t)(part * 32) * NA + a;
        const float* __restrict__ yk = ys + part * 32;
        float c0 = 0.f, c1 = 0.f, c2 = 0.f, c3 = 0.f;
        #pragma unroll
        for (int i = 0; i < 32; i += 4) {
            c0 += wv[(size_t)(i + 0) * NA] * yk[i + 0];
            c1 += wv[(size_t)(i + 1) * NA] * yk[i + 1];
            c2 += wv[(size_t)(i + 2) * NA] * yk[i + 2];
            c3 += wv[(size_t)(i + 3) * NA] * yk[i + 3];
        }
        attp[part][a] = (c0 + c1) + (c2 + c3);
    }
    __syncthreads();
    if (tid < NA)
        att[tid] = (attp[0][tid] + attp[1][tid]) + (attp[2][tid] + attp[3][tid]);
    __syncthreads();

    // ---- cand[h] = tanh(att . Wih[:,h] + hpre); 2-way a split (64 loads each)
    {
        const int half = tid >> 8;            // a in [half*64, half*64+64)
        const int h    = tid & 255;
        const float* __restrict__ wih = Wih + (size_t)(half * 64) * NH + h;
        const float* __restrict__ ak  = att + half * 64;
        float c0 = 0.f, c1 = 0.f, c2 = 0.f, c3 = 0.f;
        #pragma unroll
        for (int a = 0; a < 64; a += 4) {
            c0 += ak[a + 0] * wih[(size_t)(a + 0) * NH];
            c1 += ak[a + 1] * wih[(size_t)(a + 1) * NH];
            c2 += ak[a + 2] * wih[(size_t)(a + 2) * NH];
            c3 += ak[a + 3] * wih[(size_t)(a + 3) * NH];
        }
        candp[half][h] = (c0 + c1) + (c2 + c3);
    }
    __syncthreads();

    float* ob = out + (size_t)b * NK * NH;
    if (tid < NH)
        ob[k * NH + tid] = tanhf(g_hpre[k][tid] + candp[0][tid] + candp[1][tid]);

    // ---- passthrough k = 3..7 (done once per b, by the k==0 block), float4
    if (k == 0) {
        const float4* __restrict__ r4 = reinterpret_cast<const float4*>(rim + KACT * NH);
        float4* __restrict__ o4 = reinterpret_cast<float4*>(ob + KACT * NH);
        for (int j = tid; j < (NK - KACT) * NH / 4; j += 512)
            o4[j] = r4[j];
    }
}

// ---------------------------------------------------------------------------
extern "C" void kernel_launch(void* const* d_in, const int* in_sizes, int n_in,
                              void* d_out, int out_size)
{
    const float* x    = (const float*)d_in[0];
    const float* rim  = (const float*)d_in[1];
    const float* Wq   = (const float*)d_in[2];
    const float* Wk   = (const float*)d_in[3];
    const float* Wv   = (const float*)d_in[4];
    const float* Wih  = (const float*)d_in[5];
    const float* Whh  = (const float*)d_in[6];
    const float* bias = (const float*)d_in[7];
    float* out = (float*)d_out;

    prologue_kernel<<<KACT + 2 * KACT, 1024>>>(rim, Wq, Wk, Whh, bias);
    main_kernel<<<NB * CHUNKS, 256>>>(x);
    epilogue_kernel<<<NB * KACT, 512>>>(rim, Wv, Wih, out);
}

// round 9
// speedup vs baseline: 1.7747x; 1.0537x over previous
#include <cuda_runtime.h>
#include <cuda_bf16.h>

// Shapes: B=32, S=2048, I=128, A=128, H=256, K=8, ACTIVE=3 (structurally k=0,1,2)
#define NB 32
#define NS 2048
#define NI 128
#define NA 128
#define NH 256
#define NK 8
#define KACT 3
#define CHUNKS 32
#define ROWS_PER_BLOCK (NS / CHUNKS)       // 64
#define ROWS_PER_WARP (ROWS_PER_BLOCK / 8) // 8
#define PREF 4

// Device scratch (allocation-free rule: __device__ globals)
__device__ float g_u[KACT][NI];
__device__ float g_hpre[KACT][NH];
__device__ __align__(16) float g_ypart[NB][CHUNKS][KACT * NI];

// ---------------------------------------------------------------------------
// Prologue (9 blocks x 1024 threads):
//   blocks 0..2 : k-block. q[k][a] = sum_h rim*Wq, then u[k][i] = Wk[k][i][:].q
//   blocks 3..8 : (k, h-half) hpre
// ---------------------------------------------------------------------------
__global__ __launch_bounds__(1024) void prologue_kernel(
    const float* __restrict__ rim, const float* __restrict__ Wq,
    const float* __restrict__ Wk, const float* __restrict__ Whh,
    const float* __restrict__ bias)
{
    const int tid = threadIdx.x;
    const int bid = blockIdx.x;

    if (bid < KACT) {
        const int k = bid;
        __shared__ float qp[8][NA];
        __shared__ __align__(16) float qs[NA];

        {
            const int a    = tid & 127;
            const int part = tid >> 7;
            const int h0   = part * 32;
            const float* __restrict__ wq = Wq + ((size_t)(k * NH + h0)) * NA + a;
            const float* __restrict__ rk = rim + k * NH + h0;
            float acc0 = 0.f, acc1 = 0.f, acc2 = 0.f, acc3 = 0.f;
            #pragma unroll
            for (int h = 0; h < 32; h += 4) {
                acc0 += rk[h + 0] * wq[(size_t)(h + 0) * NA];
                acc1 += rk[h + 1] * wq[(size_t)(h + 1) * NA];
                acc2 += rk[h + 2] * wq[(size_t)(h + 2) * NA];
                acc3 += rk[h + 3] * wq[(size_t)(h + 3) * NA];
            }
            qp[part][a] = (acc0 + acc1) + (acc2 + acc3);
        }
        __syncthreads();
        if (tid < NA) {
            qs[tid] = ((qp[0][tid] + qp[1][tid]) + (qp[2][tid] + qp[3][tid]))
                    + ((qp[4][tid] + qp[5][tid]) + (qp[6][tid] + qp[7][tid]));
        }
        __syncthreads();

        const int warp = tid >> 5, lane = tid & 31;
        const float4 q4 = reinterpret_cast<const float4*>(qs)[lane];
        const float4* __restrict__ wkbase =
            reinterpret_cast<const float4*>(Wk + ((size_t)k * NI) * NA);
        #pragma unroll
        for (int ii = 0; ii < 4; ++ii) {
            const int i = warp * 4 + ii;
            const float4 w4 = wkbase[(size_t)i * 32 + lane];
            float p = w4.x * q4.x + w4.y * q4.y + w4.z * q4.z + w4.w * q4.w;
            #pragma unroll
            for (int off = 16; off; off >>= 1) p += __shfl_xor_sync(0xffffffffu, p, off);
            if (lane == 0) g_u[k][i] = p;
        }
    } else {
        const int idx  = bid - KACT;
        const int k    = idx >> 1;
        const int half = idx & 1;
        const int h    = half * 128 + (tid & 127);
        const int part = tid >> 7;
        const float* __restrict__ rk = rim + k * NH + part * 32;
        const float* __restrict__ wh = Whh + (size_t)(part * 32) * NH + h;

        float acc0 = 0.f, acc1 = 0.f, acc2 = 0.f, acc3 = 0.f;
        #pragma unroll
        for (int hp = 0; hp < 32; hp += 4) {
            acc0 += rk[hp + 0] * wh[(size_t)(hp + 0) * NH];
            acc1 += rk[hp + 1] * wh[(size_t)(hp + 1) * NH];
            acc2 += rk[hp + 2] * wh[(size_t)(hp + 2) * NH];
            acc3 += rk[hp + 3] * wh[(size_t)(hp + 3) * NH];
        }
        __shared__ float hp_s[8][128];
        hp_s[part][tid & 127] = (acc0 + acc1) + (acc2 + acc3);
        __syncthreads();
        if (tid < 128) {
            float s = ((hp_s[0][tid] + hp_s[1][tid]) + (hp_s[2][tid] + hp_s[3][tid]))
                    + ((hp_s[4][tid] + hp_s[5][tid]) + (hp_s[6][tid] + hp_s[7][tid]));
            g_hpre[k][half * 128 + tid] = bias[half * 128 + tid] + s;
        }
    }
#if __CUDA_ARCH__ >= 900
    cudaTriggerProgrammaticLaunchCompletion();
#endif
}

// ---------------------------------------------------------------------------
// Main: y[b][k][i] = sum_s x[b][s][i] * (x[b][s] . u[k]),  k = 0..2
// 1024 blocks x 256 thr. PDL: prefetch x before grid-sync, read g_u after.
// ---------------------------------------------------------------------------
__global__ __launch_bounds__(256) void main_kernel(const float* __restrict__ x)
{
    const int b     = blockIdx.x >> 5;
    const int chunk = blockIdx.x & 31;
    const int warp  = threadIdx.x >> 5;
    const int lane  = threadIdx.x & 31;

    const size_t row0 = (size_t)b * NS + chunk * ROWS_PER_BLOCK + warp * ROWS_PER_WARP;
    const float4* __restrict__ xr = reinterpret_cast<const float4*>(x + row0 * NI) + lane;

    // prefetch: x does not depend on prologue — legal pre-sync
    float4 pf[PREF];
    #pragma unroll
    for (int r = 0; r < PREF; ++r) pf[r] = xr[r * 32];

#if __CUDA_ARCH__ >= 900
    cudaGridDependencySynchronize();
#endif

    const float4 u0 = reinterpret_cast<const float4*>(g_u[0])[lane];
    const float4 u1 = reinterpret_cast<const float4*>(g_u[1])[lane];
    const float4 u2 = reinterpret_cast<const float4*>(g_u[2])[lane];

    float4 a0 = make_float4(0.f, 0.f, 0.f, 0.f);
    float4 a1 = a0, a2 = a0;

    #pragma unroll
    for (int r = 0; r < ROWS_PER_WARP; ++r) {
        const float4 v = (r < PREF) ? pf[r] : xr[r * 32];
        float d0 = v.x * u0.x + v.y * u0.y + v.z * u0.z + v.w * u0.w;
        float d1 = v.x * u1.x + v.y * u1.y + v.z * u1.z + v.w * u1.w;
        float d2 = v.x * u2.x + v.y * u2.y + v.z * u2.z + v.w * u2.w;
        #pragma unroll
        for (int off = 16; off; off >>= 1) {
            d0 += __shfl_xor_sync(0xffffffffu, d0, off);
            d1 += __shfl_xor_sync(0xffffffffu, d1, off);
            d2 += __shfl_xor_sync(0xffffffffu, d2, off);
        }
        a0.x += d0 * v.x; a0.y += d0 * v.y; a0.z += d0 * v.z; a0.w += d0 * v.w;
        a1.x += d1 * v.x; a1.y += d1 * v.y; a1.z += d1 * v.z; a1.w += d1 * v.w;
        a2.x += d2 * v.x; a2.y += d2 * v.y; a2.z += d2 * v.z; a2.w += d2 * v.w;
    }

    __shared__ __align__(16) float ysw[8][KACT * NI];
    reinterpret_cast<float4*>(&ysw[warp][0 * NI])[lane] = a0;
    reinterpret_cast<float4*>(&ysw[warp][1 * NI])[lane] = a1;
    reinterpret_cast<float4*>(&ysw[warp][2 * NI])[lane] = a2;
    __syncthreads();

    if (threadIdx.x < 96) {
        const float4* __restrict__ base = reinterpret_cast<const float4*>(ysw);
        float4 s = base[threadIdx.x];
        #pragma unroll
        for (int w = 1; w < 8; ++w) {
            const float4 t = base[w * 96 + threadIdx.x];
            s.x += t.x; s.y += t.y; s.z += t.z; s.w += t.w;
        }
        reinterpret_cast<float4*>(&g_ypart[b][chunk][0])[threadIdx.x] = s;
    }
#if __CUDA_ARCH__ >= 900
    cudaTriggerProgrammaticLaunchCompletion();
#endif
}

// ---------------------------------------------------------------------------
// Epilogue: 96 blocks (b, k) x 512 thr; all reduces 4-way split.
// ---------------------------------------------------------------------------
__global__ __launch_bounds__(512) void epilogue_kernel(
    const float* __restrict__ rim, const float* __restrict__ Wv,
    const float* __restrict__ Wih, float* __restrict__ out)
{
    const int bid = blockIdx.x;
    const int b = bid / KACT;
    const int k = bid - b * KACT;
    const int tid = threadIdx.x;

#if __CUDA_ARCH__ >= 900
    cudaGridDependencySynchronize();
#endif

    __shared__ float ysp[4][NI];
    __shared__ float ys[NI];
    __shared__ float attp[4][NA];
    __shared__ float att[NA];
    __shared__ float candp[2][NH];

    // ---- ys[i] = sum over 32 chunks; 4-way chunk split
    {
        const int part = tid >> 7;
        const int i    = tid & 127;
        const float* __restrict__ yp = &g_ypart[b][part * 8][k * NI + i];
        float s0 = yp[0 * (KACT * NI)] + yp[1 * (KACT * NI)];
        float s1 = yp[2 * (KACT * NI)] + yp[3 * (KACT * NI)];
        float s2 = yp[4 * (KACT * NI)] + yp[5 * (KACT * NI)];
        float s3 = yp[6 * (KACT * NI)] + yp[7 * (KACT * NI)];
        ysp[part][i] = (s0 + s1) + (s2 + s3);
    }
    __syncthreads();
    if (tid < NI)
        ys[tid] = (ysp[0][tid] + ysp[1][tid]) + (ysp[2][tid] + ysp[3][tid]);
    __syncthreads();

    // ---- att[a] = sum_i Wv[k][i][a] * ys[i]; 4-way i split
    {
        const int part = tid >> 7;
        const int a    = tid & 127;
        const float* __restrict__ wv = Wv + (size_t)k * NI * NA + (size_t)(part * 32) * NA + a;
        const float* __restrict__ yk = ys + part * 32;
        float c0 = 0.f, c1 = 0.f, c2 = 0.f, c3 = 0.f;
        #pragma unroll
        for (int i = 0; i < 32; i += 4) {
            c0 += wv[(size_t)(i + 0) * NA] * yk[i + 0];
            c1 += wv[(size_t)(i + 1) * NA] * yk[i + 1];
            c2 += wv[(size_t)(i + 2) * NA] * yk[i + 2];
            c3 += wv[(size_t)(i + 3) * NA] * yk[i + 3];
        }
        attp[part][a] = (c0 + c1) + (c2 + c3);
    }
    __syncthreads();
    if (tid < NA)
        att[tid] = (attp[0][tid] + attp[1][tid]) + (attp[2][tid] + attp[3][tid]);
    __syncthreads();

    // ---- cand[h]; 2-way a split
    {
        const int half = tid >> 8;
        const int h    = tid & 255;
        const float* __restrict__ wih = Wih + (size_t)(half * 64) * NH + h;
        const float* __restrict__ ak  = att + half * 64;
        float c0 = 0.f, c1 = 0.f, c2 = 0.f, c3 = 0.f;
        #pragma unroll
        for (int a = 0; a < 64; a += 4) {
            c0 += ak[a + 0] * wih[(size_t)(a + 0) * NH];
            c1 += ak[a + 1] * wih[(size_t)(a + 1) * NH];
            c2 += ak[a + 2] * wih[(size_t)(a + 2) * NH];
            c3 += ak[a + 3] * wih[(size_t)(a + 3) * NH];
        }
        candp[half][h] = (c0 + c1) + (c2 + c3);
    }
    __syncthreads();

    float* ob = out + (size_t)b * NK * NH;
    if (tid < NH)
        ob[k * NH + tid] = tanhf(g_hpre[k][tid] + candp[0][tid] + candp[1][tid]);

    if (k == 0) {
        const float4* __restrict__ r4 = reinterpret_cast<const float4*>(rim + KACT * NH);
        float4* __restrict__ o4 = reinterpret_cast<float4*>(ob + KACT * NH);
        for (int j = tid; j < (NK - KACT) * NH / 4; j += 512)
            o4[j] = r4[j];
    }
}

// ---------------------------------------------------------------------------
extern "C" void kernel_launch(void* const* d_in, const int* in_sizes, int n_in,
                              void* d_out, int out_size)
{
    const float* x    = (const float*)d_in[0];
    const float* rim  = (const float*)d_in[1];
    const float* Wq   = (const float*)d_in[2];
    const float* Wk   = (const float*)d_in[3];
    const float* Wv   = (const float*)d_in[4];
    const float* Wih  = (const float*)d_in[5];
    const float* Whh  = (const float*)d_in[6];
    const float* bias = (const float*)d_in[7];
    float* out = (float*)d_out;

    // node 1: prologue (plain launch)
    prologue_kernel<<<KACT + 2 * KACT, 1024>>>(rim, Wq, Wk, Whh, bias);

    // node 2: main with PDL — overlaps its launch/prefetch with prologue tail
    {
        cudaLaunchConfig_t cfg = {};
        cfg.gridDim  = dim3(NB * CHUNKS);
        cfg.blockDim = dim3(256);
        cudaLaunchAttribute attr[1];
        attr[0].id = cudaLaunchAttributeProgrammaticStreamSerialization;
        attr[0].val.programmaticStreamSerializationAllowed = 1;
        cfg.attrs = attr;
        cfg.numAttrs = 1;
        cudaLaunchKernelEx(&cfg, main_kernel, x);
    }

    // node 3: epilogue with PDL — overlaps its launch with main tail
    {
        cudaLaunchConfig_t cfg = {};
        cfg.gridDim  = dim3(NB * KACT);
        cfg.blockDim = dim3(512);
        cudaLaunchAttribute attr[1];
        attr[0].id = cudaLaunchAttributeProgrammaticStreamSerialization;
        attr[0].val.programmaticStreamSerializationAllowed = 1;
        cfg.attrs = attr;
        cfg.numAttrs = 1;
        cudaLaunchKernelEx(&cfg, epilogue_kernel, rim, Wv, Wih, out);
    }
}